// round 1
// baseline (speedup 1.0000x reference)
#include <cuda_runtime.h>
#include <math.h>

// Problem constants
#define BATCH 4096
#define DDIM  512
#define SLOTS 16
#define NROWS (BATCH * SLOTS)   // 65536
#define N3    (3 * DDIM)        // 1536

// ---------------------------------------------------------------------------
// Scratch buffers (device globals — no allocations allowed)
// ---------------------------------------------------------------------------
__device__ float g_Q   [(size_t)NROWS * DDIM];   // 134 MB
__device__ float g_K   [(size_t)NROWS * DDIM];
__device__ float g_V   [(size_t)NROWS * DDIM];
__device__ float g_Kx  [(size_t)BATCH * DDIM];   // 8 MB
__device__ float g_Vx  [(size_t)BATCH * DDIM];
__device__ float g_att [(size_t)NROWS * DDIM];
__device__ float g_mlp [(size_t)NROWS * DDIM];
__device__ float g_ln  [(size_t)NROWS * DDIM];
__device__ float g_cupd[(size_t)NROWS * DDIM];
__device__ float g_xz  [(size_t)BATCH * N3];     // 25 MB
__device__ float g_z   [(size_t)NROWS * N3];     // 402 MB

// ---------------------------------------------------------------------------
// Generic fp32 GEMM: C(M,N) = A(M,512) @ W(512,N)
// BM=BN=128, BK=16, 256 threads, 8x8 thread tile.
// MODE 0: plain store
// MODE 1: gates epilogue  C = sigmoid(acc + xz[row>>4, col] + bias[col])
// ---------------------------------------------------------------------------
#define BM 128
#define BN 128
#define BK 16

template <int MODE>
__global__ __launch_bounds__(256)
void gemm512(const float* __restrict__ A, const float* __restrict__ W,
             float* __restrict__ C, int N,
             const float* __restrict__ xz, const float* __restrict__ bias)
{
    __shared__ float As[BK][BM + 4];
    __shared__ float Bs[BK][BN];

    const int t  = threadIdx.x;
    const int ty = t >> 4;       // 0..15  -> rows ty*8..ty*8+7
    const int tx = t & 15;       // 0..15  -> cols tx*8..tx*8+7
    const int rowBase = blockIdx.y * BM;
    const int colBase = blockIdx.x * BN;
    const int K = 512;

    float acc[8][8];
#pragma unroll
    for (int i = 0; i < 8; i++)
#pragma unroll
        for (int j = 0; j < 8; j++) acc[i][j] = 0.f;

    for (int kt = 0; kt < K; kt += BK) {
        // A tile: 128x16 = 512 float4, 2 per thread, stored transposed
#pragma unroll
        for (int i = 0; i < 2; i++) {
            int v  = t * 2 + i;          // 0..511
            int r  = v >> 2;             // 0..127
            int k4 = (v & 3) * 4;        // 0,4,8,12
            float4 a = *reinterpret_cast<const float4*>(
                A + (size_t)(rowBase + r) * K + kt + k4);
            As[k4 + 0][r] = a.x; As[k4 + 1][r] = a.y;
            As[k4 + 2][r] = a.z; As[k4 + 3][r] = a.w;
        }
        // B tile: 16x128 = 512 float4, 2 per thread, coalesced
#pragma unroll
        for (int i = 0; i < 2; i++) {
            int v  = t + i * 256;        // 0..511
            int kk = v >> 5;             // 0..15
            int c4 = (v & 31) * 4;       // 0..124
            *reinterpret_cast<float4*>(&Bs[kk][c4]) =
                *reinterpret_cast<const float4*>(
                    W + (size_t)(kt + kk) * N + colBase + c4);
        }
        __syncthreads();

#pragma unroll
        for (int k = 0; k < BK; k++) {
            float4 a0 = *reinterpret_cast<const float4*>(&As[k][ty * 8]);
            float4 a1 = *reinterpret_cast<const float4*>(&As[k][ty * 8 + 4]);
            float4 b0 = *reinterpret_cast<const float4*>(&Bs[k][tx * 8]);
            float4 b1 = *reinterpret_cast<const float4*>(&Bs[k][tx * 8 + 4]);
            float ra[8] = {a0.x, a0.y, a0.z, a0.w, a1.x, a1.y, a1.z, a1.w};
            float rb[8] = {b0.x, b0.y, b0.z, b0.w, b1.x, b1.y, b1.z, b1.w};
#pragma unroll
            for (int i = 0; i < 8; i++)
#pragma unroll
                for (int j = 0; j < 8; j++) acc[i][j] += ra[i] * rb[j];
        }
        __syncthreads();
    }

    // epilogue + store
#pragma unroll
    for (int i = 0; i < 8; i++) {
        int row = rowBase + ty * 8 + i;
#pragma unroll
        for (int jj = 0; jj < 2; jj++) {
            int col = colBase + tx * 8 + jj * 4;
            float4 v;
            v.x = acc[i][jj * 4 + 0]; v.y = acc[i][jj * 4 + 1];
            v.z = acc[i][jj * 4 + 2]; v.w = acc[i][jj * 4 + 3];
            if (MODE == 1) {
                const float4 x4 = *reinterpret_cast<const float4*>(
                    xz + (size_t)(row >> 4) * N3 + col);
                const float4 b4 = *reinterpret_cast<const float4*>(bias + col);
                v.x = 1.f / (1.f + expf(-(v.x + x4.x + b4.x)));
                v.y = 1.f / (1.f + expf(-(v.y + x4.y + b4.y)));
                v.z = 1.f / (1.f + expf(-(v.z + x4.z + b4.z)));
                v.w = 1.f / (1.f + expf(-(v.w + x4.w + b4.w)));
            }
            *reinterpret_cast<float4*>(C + (size_t)row * N + col) = v;
        }
    }
}

// ---------------------------------------------------------------------------
// Attention: one block per batch. scores = (Q @ Km^T) * sqrt(512),
// softmax over 17, c_att = att @ V.
// ---------------------------------------------------------------------------
__global__ __launch_bounds__(256)
void attn_k(const float* __restrict__ Q, const float* __restrict__ Kc,
            const float* __restrict__ Kx, const float* __restrict__ Vc,
            const float* __restrict__ Vx, float* __restrict__ Cout)
{
    extern __shared__ float sm[];
    float* sQ = sm;                 // 16*512 = 8192
    float* sK = sQ + 8192;          // 17*512 = 8704
    float* sV = sK + 8704;          // 17*512 = 8704
    float* sS = sV + 8704;          // 16*17  = 272

    const int b = blockIdx.x;
    const int t = threadIdx.x;
    const size_t base = (size_t)b * 8192;

    for (int i = t; i < 8192; i += 256) {
        sQ[i] = Q[base + i];
        sK[i] = Kc[base + i];
        sV[i] = Vc[base + i];
    }
    for (int i = t; i < 512; i += 256) {
        sK[8192 + i] = Kx[(size_t)b * 512 + i];
        sV[8192 + i] = Vx[(size_t)b * 512 + i];
    }
    __syncthreads();

    // 272 dot products of length 512, one per (warp, iteration)
    const int w = t >> 5, lane = t & 31;
    for (int p = w; p < 272; p += 8) {          // 272/8 = 34, uniform
        int j = p / 17, l = p - j * 17;
        const float* q = sQ + j * 512;
        const float* k = sK + l * 512;
        float s = 0.f;
        for (int d = lane; d < 512; d += 32) s += q[d] * k[d];
#pragma unroll
        for (int o = 16; o; o >>= 1) s += __shfl_xor_sync(0xffffffffu, s, o);
        if (lane == 0) sS[p] = s * 22.627416997969522f;   // * sqrt(512)
    }
    __syncthreads();

    // softmax over l (17), one thread per j
    if (t < 16) {
        float m = -INFINITY;
        for (int l = 0; l < 17; l++) m = fmaxf(m, sS[t * 17 + l]);
        float sum = 0.f;
        for (int l = 0; l < 17; l++) {
            float e = expf(sS[t * 17 + l] - m);
            sS[t * 17 + l] = e;
            sum += e;
        }
        float inv = 1.f / sum;
        for (int l = 0; l < 17; l++) sS[t * 17 + l] *= inv;
    }
    __syncthreads();

    // c_att[j][d] = sum_l att[j][l] * V[l][d]; thread covers d = t, t+256
    for (int j = 0; j < 16; j++) {
        float a0 = 0.f, a1 = 0.f;
#pragma unroll
        for (int l = 0; l < 17; l++) {
            float ww = sS[j * 17 + l];
            a0 += ww * sV[l * 512 + t];
            a1 += ww * sV[l * 512 + t + 256];
        }
        Cout[base + j * 512 + t]       = a0;
        Cout[base + j * 512 + t + 256] = a1;
    }
}

// ---------------------------------------------------------------------------
// LayerNorm over rows of 512: y = gain*(x-mu)/(sd+1e-9)+bias, optional relu.
// One warp per row, 8 rows per block.
// ---------------------------------------------------------------------------
template <bool RELU>
__global__ __launch_bounds__(256)
void ln_k(const float* __restrict__ X, float* __restrict__ Y,
          const float* __restrict__ gain, const float* __restrict__ bias)
{
    const int row  = blockIdx.x * 8 + (threadIdx.x >> 5);
    const int lane = threadIdx.x & 31;
    const float4* in = reinterpret_cast<const float4*>(X + (size_t)row * 512);

    float4 v[4];
    float sum = 0.f, sq = 0.f;
#pragma unroll
    for (int i = 0; i < 4; i++) {
        v[i] = in[lane + i * 32];
        sum += v[i].x + v[i].y + v[i].z + v[i].w;
        sq  += v[i].x * v[i].x + v[i].y * v[i].y + v[i].z * v[i].z + v[i].w * v[i].w;
    }
#pragma unroll
    for (int o = 16; o; o >>= 1) {
        sum += __shfl_xor_sync(0xffffffffu, sum, o);
        sq  += __shfl_xor_sync(0xffffffffu, sq,  o);
    }
    const float mu  = sum * (1.f / 512.f);
    const float var = fmaxf(sq * (1.f / 512.f) - mu * mu, 0.f);
    const float inv = 1.f / (sqrtf(var) + 1e-9f);

    float4* out = reinterpret_cast<float4*>(Y + (size_t)row * 512);
    const float4* g4 = reinterpret_cast<const float4*>(gain);
    const float4* b4 = reinterpret_cast<const float4*>(bias);
#pragma unroll
    for (int i = 0; i < 4; i++) {
        int j = lane + i * 32;
        float4 g = g4[j], bb = b4[j], x = v[i], y;
        y.x = g.x * (x.x - mu) * inv + bb.x;
        y.y = g.y * (x.y - mu) * inv + bb.y;
        y.z = g.z * (x.z - mu) * inv + bb.z;
        y.w = g.w * (x.w - mu) * inv + bb.w;
        if (RELU) {
            y.x = fmaxf(y.x, 0.f); y.y = fmaxf(y.y, 0.f);
            y.z = fmaxf(y.z, 0.f); y.w = fmaxf(y.w, 0.f);
        }
        out[j] = y;
    }
}

// ---------------------------------------------------------------------------
// Final: c_new = f*c + i*tanh(c_upd); h_new = o*tanh(c_new).
// Writes d_out = [h_new (B*8192) | c_new (B*8192)].
// ---------------------------------------------------------------------------
__global__ __launch_bounds__(256)
void final_k(const float* __restrict__ z, const float* __restrict__ c_state,
             const float* __restrict__ cupd, float* __restrict__ out)
{
    const size_t p = (size_t)blockIdx.x * blockDim.x + threadIdx.x; // float4 idx
    const size_t flat = p * 4;                                      // < 33554432
    const size_t r = flat >> 9;
    const int    c = (int)(flat & 511);

    const float4 i4 = *reinterpret_cast<const float4*>(z + r * N3 + c);
    const float4 f4 = *reinterpret_cast<const float4*>(z + r * N3 + 512 + c);
    const float4 o4 = *reinterpret_cast<const float4*>(z + r * N3 + 1024 + c);
    const float4 c4 = *reinterpret_cast<const float4*>(c_state + flat);
    const float4 u4 = *reinterpret_cast<const float4*>(cupd + flat);

    float4 cn, hn;
    cn.x = f4.x * c4.x + i4.x * tanhf(u4.x); hn.x = o4.x * tanhf(cn.x);
    cn.y = f4.y * c4.y + i4.y * tanhf(u4.y); hn.y = o4.y * tanhf(cn.y);
    cn.z = f4.z * c4.z + i4.z * tanhf(u4.z); hn.z = o4.z * tanhf(cn.z);
    cn.w = f4.w * c4.w + i4.w * tanhf(u4.w); hn.w = o4.w * tanhf(cn.w);

    *reinterpret_cast<float4*>(out + flat) = hn;
    *reinterpret_cast<float4*>(out + (size_t)NROWS * DDIM + flat) = cn;
}

// ---------------------------------------------------------------------------
// Launch
// ---------------------------------------------------------------------------
extern "C" void kernel_launch(void* const* d_in, const int* in_sizes, int n_in,
                              void* d_out, int out_size)
{
    const float* inputs   = (const float*)d_in[0];
    const float* h_state  = (const float*)d_in[1];
    const float* c_state  = (const float*)d_in[2];
    const float* kernel_w = (const float*)d_in[3];
    const float* rec_w    = (const float*)d_in[4];
    const float* W_q      = (const float*)d_in[5];
    const float* W_k      = (const float*)d_in[6];
    const float* W_v      = (const float*)d_in[7];
    const float* mlp1     = (const float*)d_in[8];
    const float* mlp2     = (const float*)d_in[9];
    const float* gain1    = (const float*)d_in[10];
    const float* gain2    = (const float*)d_in[11];
    const float* bias1    = (const float*)d_in[12];
    const float* bias2    = (const float*)d_in[13];
    const float* bias     = (const float*)d_in[14];
    float* out = (float*)d_out;

    float *pQ, *pK, *pV, *pKx, *pVx, *pAtt, *pMlp, *pLn, *pCupd, *pXz, *pZ;
    cudaGetSymbolAddress((void**)&pQ,   g_Q);
    cudaGetSymbolAddress((void**)&pK,   g_K);
    cudaGetSymbolAddress((void**)&pV,   g_V);
    cudaGetSymbolAddress((void**)&pKx,  g_Kx);
    cudaGetSymbolAddress((void**)&pVx,  g_Vx);
    cudaGetSymbolAddress((void**)&pAtt, g_att);
    cudaGetSymbolAddress((void**)&pMlp, g_mlp);
    cudaGetSymbolAddress((void**)&pLn,  g_ln);
    cudaGetSymbolAddress((void**)&pCupd,g_cupd);
    cudaGetSymbolAddress((void**)&pXz,  g_xz);
    cudaGetSymbolAddress((void**)&pZ,   g_z);

    cudaFuncSetAttribute(attn_k, cudaFuncAttributeMaxDynamicSharedMemorySize, 103488);

    const dim3 thr(256);
    const dim3 gBig (512 / BN, NROWS / BM);   // (4, 512)  M=65536, N=512
    const dim3 gSml (512 / BN, BATCH / BM);   // (4, 32)   M=4096,  N=512
    const dim3 gXz  (N3  / BN, BATCH / BM);   // (12, 32)  M=4096,  N=1536
    const dim3 gZ   (N3  / BN, NROWS / BM);   // (12, 512) M=65536, N=1536

    // Q/K/V projections
    gemm512<0><<<gBig, thr>>>(c_state, W_q, pQ, 512, nullptr, nullptr);
    gemm512<0><<<gBig, thr>>>(c_state, W_k, pK, 512, nullptr, nullptr);
    gemm512<0><<<gSml, thr>>>(inputs,  W_k, pKx, 512, nullptr, nullptr);
    gemm512<0><<<gBig, thr>>>(c_state, W_v, pV, 512, nullptr, nullptr);
    gemm512<0><<<gSml, thr>>>(inputs,  W_v, pVx, 512, nullptr, nullptr);

    // attention (scores + softmax + weighted sum)
    attn_k<<<BATCH, 256, 103488>>>(pQ, pK, pKx, pV, pVx, pAtt);

    // MLP with layernorms (relu fused into LN1 output)
    gemm512<0><<<gBig, thr>>>(pAtt, mlp1, pMlp, 512, nullptr, nullptr);
    ln_k<true><<<NROWS / 8, 256>>>(pMlp, pLn, gain1, bias1);
    gemm512<0><<<gBig, thr>>>(pLn, mlp2, pMlp, 512, nullptr, nullptr);
    ln_k<false><<<NROWS / 8, 256>>>(pMlp, pCupd, gain2, bias2);

    // gates: xz then z = sigmoid(hz + xz + bias)
    gemm512<0><<<gXz, thr>>>(inputs, kernel_w, pXz, N3, nullptr, nullptr);
    gemm512<1><<<gZ, thr>>>(h_state, rec_w, pZ, N3, pXz, bias);

    // final elementwise -> [h_new | c_new]
    final_k<<<((size_t)NROWS * DDIM / 4) / 256, 256>>>(pZ, c_state, pCupd, out);
}

// round 3
// speedup vs baseline: 2.0711x; 2.0711x over previous
#include <cuda_runtime.h>
#include <cuda_bf16.h>
#include <math.h>
#include <stdint.h>

// Problem constants
#define BATCH 4096
#define DDIM  512
#define SLOTS 16
#define NROWS (BATCH * SLOTS)   // 65536
#define N3    (3 * DDIM)        // 1536

// ---------------------------------------------------------------------------
// Scratch buffers (device globals — no allocations allowed)
// ---------------------------------------------------------------------------
__device__ float g_Q   [(size_t)NROWS * DDIM];
__device__ float g_K   [(size_t)NROWS * DDIM];
__device__ float g_V   [(size_t)NROWS * DDIM];
__device__ float g_Kx  [(size_t)BATCH * DDIM];
__device__ float g_Vx  [(size_t)BATCH * DDIM];
__device__ float g_att [(size_t)NROWS * DDIM];
__device__ float g_mlp [(size_t)NROWS * DDIM];
__device__ float g_ln  [(size_t)NROWS * DDIM];
__device__ float g_cupd[(size_t)NROWS * DDIM];
__device__ float g_xz  [(size_t)BATCH * N3];
__device__ float g_z   [(size_t)NROWS * N3];

// Transposed + split weights: [N][K=512] bf16 hi/lo
__device__ __nv_bfloat16 g_wq_h[DDIM * DDIM], g_wq_l[DDIM * DDIM];
__device__ __nv_bfloat16 g_wk_h[DDIM * DDIM], g_wk_l[DDIM * DDIM];
__device__ __nv_bfloat16 g_wv_h[DDIM * DDIM], g_wv_l[DDIM * DDIM];
__device__ __nv_bfloat16 g_m1_h[DDIM * DDIM], g_m1_l[DDIM * DDIM];
__device__ __nv_bfloat16 g_m2_h[DDIM * DDIM], g_m2_l[DDIM * DDIM];
__device__ __nv_bfloat16 g_kr_h[DDIM * N3],  g_kr_l[DDIM * N3];
__device__ __nv_bfloat16 g_rk_h[DDIM * N3],  g_rk_l[DDIM * N3];

// ---------------------------------------------------------------------------
// Helpers
// ---------------------------------------------------------------------------
__device__ __forceinline__ uint32_t smem_u32(const void* p) {
    uint32_t a;
    asm("{ .reg .u64 t; cvta.to.shared.u64 t, %1; cvt.u32.u64 %0, t; }"
        : "=r"(a) : "l"(p));
    return a;
}
__device__ __forceinline__ uint32_t pack2(__nv_bfloat16 a, __nv_bfloat16 b) {
    return (uint32_t)__bfloat16_as_ushort(a) |
           ((uint32_t)__bfloat16_as_ushort(b) << 16);
}

#define CP16(dst, src) \
    asm volatile("cp.async.ca.shared.global [%0], [%1], 16;" \
                 :: "r"(dst), "l"(src) : "memory")
#define CP_COMMIT()  asm volatile("cp.async.commit_group;" ::: "memory")
#define CP_WAIT0()   asm volatile("cp.async.wait_group 0;" ::: "memory")

#define LDSM4(r0, r1, r2, r3, addr) \
    asm volatile("ldmatrix.sync.aligned.m8n8.x4.shared.b16 {%0,%1,%2,%3}, [%4];" \
                 : "=r"(r0), "=r"(r1), "=r"(r2), "=r"(r3) : "r"(addr))

#define MMA_BF16(ac, a0, a1, a2, a3, b0, b1) \
    asm volatile("mma.sync.aligned.m16n8k16.row.col.f32.bf16.bf16.f32 " \
                 "{%0,%1,%2,%3},{%4,%5,%6,%7},{%8,%9},{%0,%1,%2,%3};" \
                 : "+f"((ac)[0]), "+f"((ac)[1]), "+f"((ac)[2]), "+f"((ac)[3]) \
                 : "r"(a0), "r"(a1), "r"(a2), "r"(a3), "r"(b0), "r"(b1))

// ---------------------------------------------------------------------------
// Weight prep: W [512][N] fp32 -> Wt_hi/Wt_lo [N][512] bf16 (split)
// ---------------------------------------------------------------------------
__global__ __launch_bounds__(256)
void prep_w(const float* __restrict__ W, __nv_bfloat16* __restrict__ Wh,
            __nv_bfloat16* __restrict__ Wl, int N)
{
    int idx = blockIdx.x * 256 + threadIdx.x;
    int k = idx / N, n = idx - k * N;
    float x = W[idx];
    __nv_bfloat16 h = __float2bfloat16(x);
    float r = x - __bfloat162float(h);
    Wh[(size_t)n * 512 + k] = h;
    Wl[(size_t)n * 512 + k] = __float2bfloat16(r);
}

// ---------------------------------------------------------------------------
// mma.sync bf16-split GEMM: C(M,N) = A(M,512) @ W(512,N)
// W pre-split/transposed to [N][512] bf16 hi/lo.
// 3-term emulation: Ah*Bh + Al*Bh + Ah*Bl, fp32 accumulate.
// CTA: 128x256, BK=32, 8 warps (2x4), warp tile 64x64, double-buffered smem.
// MODE 0: plain store. MODE 1: C = sigmoid(acc + xz[row>>4, col] + bias[col]).
// ---------------------------------------------------------------------------
#define TM 128
#define TN 256
#define TK 32
#define NCH 16                      // 512 / 32
#define RSB 80                      // smem row pitch (bytes) = 32*2 + 16 pad
#define OFF_AH 0
#define OFF_AL (128 * RSB)          // 10240
#define OFF_BH (2 * 128 * RSB)      // 20480
#define OFF_BL (2 * 128 * RSB + 256 * RSB)  // 40960
#define STAGE_B (2 * 128 * RSB + 2 * 256 * RSB)  // 61440
#define GEMM_SMEM (2 * STAGE_B)     // 122880

template <int MODE>
__global__ __launch_bounds__(256, 1)
void tc_gemm(const float* __restrict__ A,
             const __nv_bfloat16* __restrict__ Bh,
             const __nv_bfloat16* __restrict__ Bl,
             float* __restrict__ C, int N,
             const float* __restrict__ xz, const float* __restrict__ bias)
{
    extern __shared__ char smem[];
    const uint32_t tb = smem_u32(smem);

    const int t    = threadIdx.x;
    const int w    = t >> 5;
    const int lane = t & 31;
    const int wm   = w >> 2;          // 0..1
    const int wn   = w & 3;           // 0..3
    const int wmBase = wm * 64;
    const int wnBase = wn * 64;
    const int rowBase = blockIdx.y * TM;
    const int nBase   = blockIdx.x * TN;

    // ldmatrix per-lane address components
    const uint32_t aRow = (uint32_t)(lane & 15);
    const uint32_t aK   = (uint32_t)((lane >> 4) * 8);
    const uint32_t bRow = (uint32_t)((lane & 7) + ((lane >> 4) << 3));
    const uint32_t bK   = (uint32_t)(((lane >> 3) & 1) * 8);

    float acc[4][8][4];
#pragma unroll
    for (int i = 0; i < 4; i++)
#pragma unroll
        for (int j = 0; j < 8; j++)
#pragma unroll
            for (int q = 0; q < 4; q++) acc[i][j][q] = 0.f;

    float4 aR[2];

    auto loadA = [&](int c) {
#pragma unroll
        for (int i = 0; i < 2; i++) {
            int v = i * 256 + t;          // 0..511 (128 rows * 4 float4)
            int r = v >> 2, c4 = v & 3;   // 4 float4 per row of 16... (32 floats = 8 f4)
            // 128 rows * 8 float4 = 1024 f4; 512 slots*2 iters -> 2 f4/thread? fix:
            (void)r; (void)c4;
        }
        // 128 rows x 32 floats = 4096 floats = 1024 float4 -> 4 per thread
#pragma unroll
        for (int i = 0; i < 2; i++) {
            int v = i * 512 + (t << 1);   // even pairs: handle 2 consecutive f4
            int r = v >> 3, c4 = v & 7;
            const float4* src = reinterpret_cast<const float4*>(
                A + (size_t)(rowBase + r) * 512 + c * TK) + c4;
            aR[i] = *src;
        }
    };
    // NOTE: loadA above loads 2 float4 per thread = 512 f4 total (half the tile);
    // second half handled by a second register pair below.
    float4 aR2[2];
    auto loadA2 = [&](int c) {
#pragma unroll
        for (int i = 0; i < 2; i++) {
            int v = i * 512 + (t << 1) + 1;
            int r = v >> 3, c4 = v & 7;
            const float4* src = reinterpret_cast<const float4*>(
                A + (size_t)(rowBase + r) * 512 + c * TK) + c4;
            aR2[i] = *src;
        }
    };

    auto storeA = [&](int s) {
        const uint32_t baseH = tb + s * STAGE_B + OFF_AH;
        const uint32_t baseL = tb + s * STAGE_B + OFF_AL;
#pragma unroll
        for (int i = 0; i < 2; i++) {
#pragma unroll
            for (int half = 0; half < 2; half++) {
                int v = i * 512 + (t << 1) + half;
                int r = v >> 3, c4 = v & 7;
                float4 x = half ? aR2[i] : aR[i];
                __nv_bfloat16 h0 = __float2bfloat16(x.x), h1 = __float2bfloat16(x.y);
                __nv_bfloat16 h2 = __float2bfloat16(x.z), h3 = __float2bfloat16(x.w);
                __nv_bfloat16 l0 = __float2bfloat16(x.x - __bfloat162float(h0));
                __nv_bfloat16 l1 = __float2bfloat16(x.y - __bfloat162float(h1));
                __nv_bfloat16 l2 = __float2bfloat16(x.z - __bfloat162float(h2));
                __nv_bfloat16 l3 = __float2bfloat16(x.w - __bfloat162float(h3));
                uint32_t off = (uint32_t)(r * RSB + c4 * 8);
                asm volatile("st.shared.v2.b32 [%0], {%1,%2};"
                             :: "r"(baseH + off), "r"(pack2(h0, h1)), "r"(pack2(h2, h3))
                             : "memory");
                asm volatile("st.shared.v2.b32 [%0], {%1,%2};"
                             :: "r"(baseL + off), "r"(pack2(l0, l1)), "r"(pack2(l2, l3))
                             : "memory");
            }
        }
    };

    auto issueB = [&](int c, int s) {
        const uint32_t dH = tb + s * STAGE_B + OFF_BH;
        const uint32_t dL = tb + s * STAGE_B + OFF_BL;
        const int kb = c * TK;
#pragma unroll
        for (int i = 0; i < 4; i++) {
            int v = i * 256 + t;            // 1024 chunks of 16B (256 rows x 4)
            int row = v >> 2, seg = v & 3;
            const size_t so = (size_t)(nBase + row) * 512 + kb + seg * 8;
            uint32_t doff = (uint32_t)(row * RSB + seg * 16);
            CP16(dH + doff, Bh + so);
            CP16(dL + doff, Bl + so);
        }
        CP_COMMIT();
    };

    auto compute = [&](int s) {
        const uint32_t sAh = tb + s * STAGE_B + OFF_AH;
        const uint32_t sAl = tb + s * STAGE_B + OFF_AL;
        const uint32_t sBh = tb + s * STAGE_B + OFF_BH;
        const uint32_t sBl = tb + s * STAGE_B + OFF_BL;
#pragma unroll
        for (int kk = 0; kk < TK; kk += 16) {
            uint32_t bh[4][4], bl[4][4];
#pragma unroll
            for (int p = 0; p < 4; p++) {
                uint32_t addr = (uint32_t)((wnBase + p * 16 + bRow) * RSB + (kk + bK) * 2);
                LDSM4(bh[p][0], bh[p][1], bh[p][2], bh[p][3], sBh + addr);
                LDSM4(bl[p][0], bl[p][1], bl[p][2], bl[p][3], sBl + addr);
            }
#pragma unroll
            for (int mi = 0; mi < 4; mi++) {
                uint32_t addr = (uint32_t)((wmBase + mi * 16 + aRow) * RSB + (kk + aK) * 2);
                uint32_t ah0, ah1, ah2, ah3, al0, al1, al2, al3;
                LDSM4(ah0, ah1, ah2, ah3, sAh + addr);
                LDSM4(al0, al1, al2, al3, sAl + addr);
#pragma unroll
                for (int g = 0; g < 8; g++) {
                    int p = g >> 1, q = (g & 1) * 2;
                    MMA_BF16(acc[mi][g], ah0, ah1, ah2, ah3, bh[p][q], bh[p][q + 1]);
                    MMA_BF16(acc[mi][g], al0, al1, al2, al3, bh[p][q], bh[p][q + 1]);
                    MMA_BF16(acc[mi][g], ah0, ah1, ah2, ah3, bl[p][q], bl[p][q + 1]);
                }
            }
        }
    };

    // prologue: stage 0
    loadA(0); loadA2(0);
    storeA(0);
    issueB(0, 0);

    for (int c = 0; c < NCH; c++) {
        const int s = c & 1;
        CP_WAIT0();
        __syncthreads();
        if (c + 1 < NCH) {
            loadA(c + 1); loadA2(c + 1);
            issueB(c + 1, s ^ 1);
        }
        compute(s);
        if (c + 1 < NCH) storeA(s ^ 1);
    }

    // epilogue: direct register -> gmem stores (32B-sector-aligned float2)
    const int tr  = lane >> 2;
    const int tc2 = (lane & 3) * 2;
#pragma unroll
    for (int mi = 0; mi < 4; mi++) {
#pragma unroll
        for (int g = 0; g < 8; g++) {
            int row = rowBase + wmBase + mi * 16 + tr;
            int col = nBase + wnBase + g * 8 + tc2;
            float v0 = acc[mi][g][0], v1 = acc[mi][g][1];
            float v2 = acc[mi][g][2], v3 = acc[mi][g][3];
            if (MODE == 1) {
                const float* xr0 = xz + (size_t)(row >> 4) * N3 + col;
                const float* xr1 = xz + (size_t)((row + 8) >> 4) * N3 + col;
                float b0 = bias[col], b1 = bias[col + 1];
                v0 = 1.f / (1.f + expf(-(v0 + xr0[0] + b0)));
                v1 = 1.f / (1.f + expf(-(v1 + xr0[1] + b1)));
                v2 = 1.f / (1.f + expf(-(v2 + xr1[0] + b0)));
                v3 = 1.f / (1.f + expf(-(v3 + xr1[1] + b1)));
            }
            *reinterpret_cast<float2*>(C + (size_t)row * N + col)       = make_float2(v0, v1);
            *reinterpret_cast<float2*>(C + (size_t)(row + 8) * N + col) = make_float2(v2, v3);
        }
    }
}

// ---------------------------------------------------------------------------
// Attention: one block per batch (unchanged)
// ---------------------------------------------------------------------------
__global__ __launch_bounds__(256)
void attn_k(const float* __restrict__ Q, const float* __restrict__ Kc,
            const float* __restrict__ Kx, const float* __restrict__ Vc,
            const float* __restrict__ Vx, float* __restrict__ Cout)
{
    extern __shared__ float sm[];
    float* sQ = sm;
    float* sK = sQ + 8192;
    float* sV = sK + 8704;
    float* sS = sV + 8704;

    const int b = blockIdx.x;
    const int t = threadIdx.x;
    const size_t base = (size_t)b * 8192;

    for (int i = t; i < 8192; i += 256) {
        sQ[i] = Q[base + i];
        sK[i] = Kc[base + i];
        sV[i] = Vc[base + i];
    }
    for (int i = t; i < 512; i += 256) {
        sK[8192 + i] = Kx[(size_t)b * 512 + i];
        sV[8192 + i] = Vx[(size_t)b * 512 + i];
    }
    __syncthreads();

    const int w = t >> 5, lane = t & 31;
    for (int p = w; p < 272; p += 8) {
        int j = p / 17, l = p - j * 17;
        const float* q = sQ + j * 512;
        const float* k = sK + l * 512;
        float s = 0.f;
        for (int d = lane; d < 512; d += 32) s += q[d] * k[d];
#pragma unroll
        for (int o = 16; o; o >>= 1) s += __shfl_xor_sync(0xffffffffu, s, o);
        if (lane == 0) sS[p] = s * 22.627416997969522f;
    }
    __syncthreads();

    if (t < 16) {
        float m = -INFINITY;
        for (int l = 0; l < 17; l++) m = fmaxf(m, sS[t * 17 + l]);
        float sum = 0.f;
        for (int l = 0; l < 17; l++) {
            float e = expf(sS[t * 17 + l] - m);
            sS[t * 17 + l] = e;
            sum += e;
        }
        float inv = 1.f / sum;
        for (int l = 0; l < 17; l++) sS[t * 17 + l] *= inv;
    }
    __syncthreads();

    for (int j = 0; j < 16; j++) {
        float a0 = 0.f, a1 = 0.f;
#pragma unroll
        for (int l = 0; l < 17; l++) {
            float ww = sS[j * 17 + l];
            a0 += ww * sV[l * 512 + t];
            a1 += ww * sV[l * 512 + t + 256];
        }
        Cout[base + j * 512 + t]       = a0;
        Cout[base + j * 512 + t + 256] = a1;
    }
}

// ---------------------------------------------------------------------------
// LayerNorm (unchanged)
// ---------------------------------------------------------------------------
template <bool RELU>
__global__ __launch_bounds__(256)
void ln_k(const float* __restrict__ X, float* __restrict__ Y,
          const float* __restrict__ gain, const float* __restrict__ bias)
{
    const int row  = blockIdx.x * 8 + (threadIdx.x >> 5);
    const int lane = threadIdx.x & 31;
    const float4* in = reinterpret_cast<const float4*>(X + (size_t)row * 512);

    float4 v[4];
    float sum = 0.f, sq = 0.f;
#pragma unroll
    for (int i = 0; i < 4; i++) {
        v[i] = in[lane + i * 32];
        sum += v[i].x + v[i].y + v[i].z + v[i].w;
        sq  += v[i].x * v[i].x + v[i].y * v[i].y + v[i].z * v[i].z + v[i].w * v[i].w;
    }
#pragma unroll
    for (int o = 16; o; o >>= 1) {
        sum += __shfl_xor_sync(0xffffffffu, sum, o);
        sq  += __shfl_xor_sync(0xffffffffu, sq,  o);
    }
    const float mu  = sum * (1.f / 512.f);
    const float var = fmaxf(sq * (1.f / 512.f) - mu * mu, 0.f);
    const float inv = 1.f / (sqrtf(var) + 1e-9f);

    float4* out = reinterpret_cast<float4*>(Y + (size_t)row * 512);
    const float4* g4 = reinterpret_cast<const float4*>(gain);
    const float4* b4 = reinterpret_cast<const float4*>(bias);
#pragma unroll
    for (int i = 0; i < 4; i++) {
        int j = lane + i * 32;
        float4 g = g4[j], bb = b4[j], x = v[i], y;
        y.x = g.x * (x.x - mu) * inv + bb.x;
        y.y = g.y * (x.y - mu) * inv + bb.y;
        y.z = g.z * (x.z - mu) * inv + bb.z;
        y.w = g.w * (x.w - mu) * inv + bb.w;
        if (RELU) {
            y.x = fmaxf(y.x, 0.f); y.y = fmaxf(y.y, 0.f);
            y.z = fmaxf(y.z, 0.f); y.w = fmaxf(y.w, 0.f);
        }
        out[j] = y;
    }
}

// ---------------------------------------------------------------------------
// Final elementwise (unchanged)
// ---------------------------------------------------------------------------
__global__ __launch_bounds__(256)
void final_k(const float* __restrict__ z, const float* __restrict__ c_state,
             const float* __restrict__ cupd, float* __restrict__ out)
{
    const size_t p = (size_t)blockIdx.x * blockDim.x + threadIdx.x;
    const size_t flat = p * 4;
    const size_t r = flat >> 9;
    const int    c = (int)(flat & 511);

    const float4 i4 = *reinterpret_cast<const float4*>(z + r * N3 + c);
    const float4 f4 = *reinterpret_cast<const float4*>(z + r * N3 + 512 + c);
    const float4 o4 = *reinterpret_cast<const float4*>(z + r * N3 + 1024 + c);
    const float4 c4 = *reinterpret_cast<const float4*>(c_state + flat);
    const float4 u4 = *reinterpret_cast<const float4*>(cupd + flat);

    float4 cn, hn;
    cn.x = f4.x * c4.x + i4.x * tanhf(u4.x); hn.x = o4.x * tanhf(cn.x);
    cn.y = f4.y * c4.y + i4.y * tanhf(u4.y); hn.y = o4.y * tanhf(cn.y);
    cn.z = f4.z * c4.z + i4.z * tanhf(u4.z); hn.z = o4.z * tanhf(cn.z);
    cn.w = f4.w * c4.w + i4.w * tanhf(u4.w); hn.w = o4.w * tanhf(cn.w);

    *reinterpret_cast<float4*>(out + flat) = hn;
    *reinterpret_cast<float4*>(out + (size_t)NROWS * DDIM + flat) = cn;
}

// ---------------------------------------------------------------------------
// Launch
// ---------------------------------------------------------------------------
extern "C" void kernel_launch(void* const* d_in, const int* in_sizes, int n_in,
                              void* d_out, int out_size)
{
    const float* inputs   = (const float*)d_in[0];
    const float* h_state  = (const float*)d_in[1];
    const float* c_state  = (const float*)d_in[2];
    const float* kernel_w = (const float*)d_in[3];
    const float* rec_w    = (const float*)d_in[4];
    const float* W_q      = (const float*)d_in[5];
    const float* W_k      = (const float*)d_in[6];
    const float* W_v      = (const float*)d_in[7];
    const float* mlp1     = (const float*)d_in[8];
    const float* mlp2     = (const float*)d_in[9];
    const float* gain1    = (const float*)d_in[10];
    const float* gain2    = (const float*)d_in[11];
    const float* bias1    = (const float*)d_in[12];
    const float* bias2    = (const float*)d_in[13];
    const float* bias     = (const float*)d_in[14];
    float* out = (float*)d_out;

    float *pQ, *pK, *pV, *pKx, *pVx, *pAtt, *pMlp, *pLn, *pCupd, *pXz, *pZ;
    cudaGetSymbolAddress((void**)&pQ,   g_Q);
    cudaGetSymbolAddress((void**)&pK,   g_K);
    cudaGetSymbolAddress((void**)&pV,   g_V);
    cudaGetSymbolAddress((void**)&pKx,  g_Kx);
    cudaGetSymbolAddress((void**)&pVx,  g_Vx);
    cudaGetSymbolAddress((void**)&pAtt, g_att);
    cudaGetSymbolAddress((void**)&pMlp, g_mlp);
    cudaGetSymbolAddress((void**)&pLn,  g_ln);
    cudaGetSymbolAddress((void**)&pCupd,g_cupd);
    cudaGetSymbolAddress((void**)&pXz,  g_xz);
    cudaGetSymbolAddress((void**)&pZ,   g_z);

    __nv_bfloat16 *wqh,*wql,*wkh,*wkl,*wvh,*wvl,*m1h,*m1l,*m2h,*m2l,*krh,*krl,*rkh,*rkl;
    cudaGetSymbolAddress((void**)&wqh, g_wq_h); cudaGetSymbolAddress((void**)&wql, g_wq_l);
    cudaGetSymbolAddress((void**)&wkh, g_wk_h); cudaGetSymbolAddress((void**)&wkl, g_wk_l);
    cudaGetSymbolAddress((void**)&wvh, g_wv_h); cudaGetSymbolAddress((void**)&wvl, g_wv_l);
    cudaGetSymbolAddress((void**)&m1h, g_m1_h); cudaGetSymbolAddress((void**)&m1l, g_m1_l);
    cudaGetSymbolAddress((void**)&m2h, g_m2_h); cudaGetSymbolAddress((void**)&m2l, g_m2_l);
    cudaGetSymbolAddress((void**)&krh, g_kr_h); cudaGetSymbolAddress((void**)&krl, g_kr_l);
    cudaGetSymbolAddress((void**)&rkh, g_rk_h); cudaGetSymbolAddress((void**)&rkl, g_rk_l);

    cudaFuncSetAttribute(attn_k, cudaFuncAttributeMaxDynamicSharedMemorySize, 103488);
    cudaFuncSetAttribute(tc_gemm<0>, cudaFuncAttributeMaxDynamicSharedMemorySize, GEMM_SMEM);
    cudaFuncSetAttribute(tc_gemm<1>, cudaFuncAttributeMaxDynamicSharedMemorySize, GEMM_SMEM);

    const dim3 thr(256);

    // weight prep (transpose + bf16 split)
    prep_w<<<(DDIM * DDIM) / 256, thr>>>(W_q,      wqh, wql, DDIM);
    prep_w<<<(DDIM * DDIM) / 256, thr>>>(W_k,      wkh, wkl, DDIM);
    prep_w<<<(DDIM * DDIM) / 256, thr>>>(W_v,      wvh, wvl, DDIM);
    prep_w<<<(DDIM * DDIM) / 256, thr>>>(mlp1,     m1h, m1l, DDIM);
    prep_w<<<(DDIM * DDIM) / 256, thr>>>(mlp2,     m2h, m2l, DDIM);
    prep_w<<<(DDIM * N3)   / 256, thr>>>(kernel_w, krh, krl, N3);
    prep_w<<<(DDIM * N3)   / 256, thr>>>(rec_w,    rkh, rkl, N3);

    const dim3 gBig(2, NROWS / TM);    // M=65536, N=512
    const dim3 gSml(2, BATCH / TM);    // M=4096,  N=512
    const dim3 gXz (6, BATCH / TM);    // M=4096,  N=1536
    const dim3 gZ  (6, NROWS / TM);    // M=65536, N=1536

    // Q/K/V projections
    tc_gemm<0><<<gBig, thr, GEMM_SMEM>>>(c_state, wqh, wql, pQ, 512, nullptr, nullptr);
    tc_gemm<0><<<gBig, thr, GEMM_SMEM>>>(c_state, wkh, wkl, pK, 512, nullptr, nullptr);
    tc_gemm<0><<<gSml, thr, GEMM_SMEM>>>(inputs,  wkh, wkl, pKx, 512, nullptr, nullptr);
    tc_gemm<0><<<gBig, thr, GEMM_SMEM>>>(c_state, wvh, wvl, pV, 512, nullptr, nullptr);
    tc_gemm<0><<<gSml, thr, GEMM_SMEM>>>(inputs,  wvh, wvl, pVx, 512, nullptr, nullptr);

    // attention
    attn_k<<<BATCH, thr, 103488>>>(pQ, pK, pKx, pV, pVx, pAtt);

    // MLP + layernorms
    tc_gemm<0><<<gBig, thr, GEMM_SMEM>>>(pAtt, m1h, m1l, pMlp, 512, nullptr, nullptr);
    ln_k<true><<<NROWS / 8, thr>>>(pMlp, pLn, gain1, bias1);
    tc_gemm<0><<<gBig, thr, GEMM_SMEM>>>(pLn, m2h, m2l, pMlp, 512, nullptr, nullptr);
    ln_k<false><<<NROWS / 8, thr>>>(pMlp, pCupd, gain2, bias2);

    // gates
    tc_gemm<0><<<gXz, thr, GEMM_SMEM>>>(inputs,  krh, krl, pXz, N3, nullptr, nullptr);
    tc_gemm<1><<<gZ,  thr, GEMM_SMEM>>>(h_state, rkh, rkl, pZ,  N3, pXz, bias);

    // final elementwise -> [h_new | c_new]
    final_k<<<((size_t)NROWS * DDIM / 4) / 256, thr>>>(pZ, c_state, pCupd, out);
}